// round 14
// baseline (speedup 1.0000x reference)
#include <cuda_runtime.h>
#include <cuda_bf16.h>
#include <math.h>
#include <cstdint>

#define B_SZ 2
#define NTOK 2048
#define NH 8
#define DK 64
#define DM 512
#define NQT 32                 // 64-row tiles per sequence
#define INF_F __int_as_float(0x7f800000)

// device scratch
__device__ float g_o[B_SZ * NTOK * DM];
__device__ __align__(16) __nv_bfloat16 g_qhi[B_SZ * NH * NTOK * DK];
__device__ __align__(16) __nv_bfloat16 g_qlo[B_SZ * NH * NTOK * DK];
__device__ __align__(16) __nv_bfloat16 g_khi[B_SZ * NH * NTOK * DK];
__device__ __align__(16) __nv_bfloat16 g_klo[B_SZ * NH * NTOK * DK];
__device__ __align__(16) __nv_bfloat16 g_vhi[B_SZ * NH * NTOK * DK];
__device__ __align__(16) __nv_bfloat16 g_vlo[B_SZ * NH * NTOK * DK];
__device__ __align__(16) __nv_bfloat16 g_xhi[3 * B_SZ * NTOK * DM];
__device__ __align__(16) __nv_bfloat16 g_xlo[3 * B_SZ * NTOK * DM];
__device__ __align__(16) __nv_bfloat16 g_whi[3 * NH * DK * DM];
__device__ __align__(16) __nv_bfloat16 g_wlo[3 * NH * DK * DM];
// spatial sort state
__device__ int g_perm[B_SZ * NTOK];                 // sorted pos -> orig token
__device__ int g_ipos[B_SZ * NTOK];                 // orig token -> sorted pos
__device__ __align__(16) float g_scoords[B_SZ * NTOK * 3];
__device__ __align__(16) unsigned char g_skpm[B_SZ * NTOK];
__device__ float g_bbox[B_SZ * NQT * 6];            // mn x,y,z, mx x,y,z
__device__ int g_tcnt[B_SZ * NH * NQT];
__device__ int g_tlist[B_SZ * NH * NQT * NQT];

// ---------------- helpers ----------------
__device__ __forceinline__ uint32_t smem_to_u32(const void* p) {
    uint32_t a;
    asm("{ .reg .u64 t; cvta.to.shared.u64 t, %1; cvt.u32.u64 %0, t; }" : "=r"(a) : "l"(p));
    return a;
}

#define LDMX2(r0, r1, addr) \
    asm volatile("ldmatrix.sync.aligned.m8n8.x2.shared.b16 {%0,%1}, [%2];" \
        : "=r"(r0), "=r"(r1) : "r"(addr))
#define LDMX4(r, addr) \
    asm volatile("ldmatrix.sync.aligned.m8n8.x4.shared.b16 {%0,%1,%2,%3}, [%4];" \
        : "=r"((r)[0]), "=r"((r)[1]), "=r"((r)[2]), "=r"((r)[3]) : "r"(addr))
#define LDMX4T(r, addr) \
    asm volatile("ldmatrix.sync.aligned.m8n8.x4.trans.shared.b16 {%0,%1,%2,%3}, [%4];" \
        : "=r"((r)[0]), "=r"((r)[1]), "=r"((r)[2]), "=r"((r)[3]) : "r"(addr))
#define MMA16816(d, a, b0, b1) \
    asm volatile("mma.sync.aligned.m16n8k16.row.col.f32.bf16.bf16.f32 " \
        "{%0,%1,%2,%3}, {%4,%5,%6,%7}, {%8,%9}, {%0,%1,%2,%3};" \
        : "+f"((d)[0]), "+f"((d)[1]), "+f"((d)[2]), "+f"((d)[3]) \
        : "r"((a)[0]), "r"((a)[1]), "r"((a)[2]), "r"((a)[3]), "r"(b0), "r"(b1))

#define CP_ASYNC16(dst, src) \
    asm volatile("cp.async.cg.shared.global [%0], [%1], 16;" :: "r"(dst), "l"(src) : "memory")
#define CP_COMMIT()  asm volatile("cp.async.commit_group;" ::: "memory")
#define CP_WAIT1()   asm volatile("cp.async.wait_group 1;" ::: "memory")
#define CP_WAIT0()   asm volatile("cp.async.wait_group 0;" ::: "memory")

__device__ __forceinline__ uint32_t pack_split(float a, float b, uint32_t& lo) {
    __nv_bfloat162 hv = __float22bfloat162_rn(make_float2(a, b));
    float ra = a - __low2float(hv);
    float rb = b - __high2float(hv);
    __nv_bfloat162 lv = __float22bfloat162_rn(make_float2(ra, rb));
    lo = *reinterpret_cast<uint32_t*>(&lv);
    return *reinterpret_cast<uint32_t*>(&hv);
}

__device__ __forceinline__ void stage8(const float* __restrict__ src,
                                       char* hi_dst, char* lo_dst)
{
    float4 a = ((const float4*)src)[0];
    float4 b = ((const float4*)src)[1];
    uint32_t l0, l1, l2, l3;
    uint32_t h0 = pack_split(a.x, a.y, l0);
    uint32_t h1 = pack_split(a.z, a.w, l1);
    uint32_t h2 = pack_split(b.x, b.y, l2);
    uint32_t h3 = pack_split(b.z, b.w, l3);
    *(uint4*)hi_dst = make_uint4(h0, h1, h2, h3);
    *(uint4*)lo_dst = make_uint4(l0, l1, l2, l3);
}

__device__ __forceinline__ float head_spread(int h) {
    float tpow = 0.98f * (float)h / 7.0f;
    return 3.7f + (powf(20.0f, tpow) - 1.0f) * (16.3f / 19.0f);
}

// ============================================================
// pre-split kernels
// ============================================================
__global__ __launch_bounds__(256) void presplit_x_kernel(
    const float* __restrict__ q, const float* __restrict__ k, const float* __restrict__ v)
{
    const int z = blockIdx.y;
    const float* X = (z == 0) ? q : (z == 1) ? k : v;
    size_t off = ((size_t)blockIdx.x * 256 + threadIdx.x) * 8;
    size_t base = (size_t)z * (B_SZ * NTOK * DM) + off;
    stage8(X + off, (char*)(g_xhi + base), (char*)(g_xlo + base));
}

__global__ __launch_bounds__(256) void presplit_w_kernel(
    const float* __restrict__ qp, const float* __restrict__ kpj, const float* __restrict__ vp)
{
    const int z = blockIdx.y;
    const float* W = (z == 0) ? qp : (z == 1) ? kpj : vp;
    int t = blockIdx.x * 256 + threadIdx.x;
    int kc = t & 63, n = (t >> 6) & 63, h = t >> 12;
    int k0 = kc * 8;
    float f[8];
#pragma unroll
    for (int e = 0; e < 8; e++)
        f[e] = W[(size_t)h * DM * DK + (size_t)(k0 + e) * DK + n];
    uint32_t hp[4], lp[4];
#pragma unroll
    for (int e = 0; e < 4; e++)
        hp[e] = pack_split(f[2*e], f[2*e+1], lp[e]);
    size_t base = (((size_t)z * NH + h) * DK + n) * DM + k0;
    *(uint4*)(g_whi + base) = make_uint4(hp[0], hp[1], hp[2], hp[3]);
    *(uint4*)(g_wlo + base) = make_uint4(lp[0], lp[1], lp[2], lp[3]);
}

// ============================================================
// spatial sort: deterministic Morton counting sort, per batch.
// One 512-thread block per b. Also gathers coords/kpm and builds tile bboxes.
// ============================================================
__global__ __launch_bounds__(512) void sort_kernel(
    const float* __restrict__ coords, const unsigned char* __restrict__ kpm)
{
    const int b = blockIdx.x, tid = threadIdx.x;
    __shared__ float sx[NTOK], sy[NTOK], sz[NTOK];
    __shared__ int scell[NTOK];
    __shared__ int sbase[512];
    __shared__ float pmn[512][3], pmx0[512][3];
    __shared__ float bounds[6];

    for (int i = tid; i < NTOK; i += 512) {
        const float* cp = coords + ((size_t)b * NTOK + i) * 3;
        sx[i] = cp[0]; sy[i] = cp[1]; sz[i] = cp[2];
    }
    __syncthreads();

    // min/max reduction
    float mn[3] = {1e30f, 1e30f, 1e30f}, mx[3] = {-1e30f, -1e30f, -1e30f};
    for (int i = tid; i < NTOK; i += 512) {
        mn[0] = fminf(mn[0], sx[i]); mx[0] = fmaxf(mx[0], sx[i]);
        mn[1] = fminf(mn[1], sy[i]); mx[1] = fmaxf(mx[1], sy[i]);
        mn[2] = fminf(mn[2], sz[i]); mx[2] = fmaxf(mx[2], sz[i]);
    }
#pragma unroll
    for (int d = 0; d < 3; d++) { pmn[tid][d] = mn[d]; pmx0[tid][d] = mx[d]; }
    __syncthreads();
    if (tid == 0) {
        float a[3] = {1e30f, 1e30f, 1e30f}, c[3] = {-1e30f, -1e30f, -1e30f};
        for (int t = 0; t < 512; t++)
#pragma unroll
            for (int d = 0; d < 3; d++) {
                a[d] = fminf(a[d], pmn[t][d]);
                c[d] = fmaxf(c[d], pmx0[t][d]);
            }
#pragma unroll
        for (int d = 0; d < 3; d++) { bounds[d] = a[d]; bounds[3 + d] = c[d]; }
    }
    __syncthreads();

    const float ivx = 8.0f / (bounds[3] - bounds[0] + 1e-4f);
    const float ivy = 8.0f / (bounds[4] - bounds[1] + 1e-4f);
    const float ivz = 8.0f / (bounds[5] - bounds[2] + 1e-4f);

    for (int i = tid; i < 512; i += 512) sbase[i] = 0;
    __syncthreads();

    for (int i = tid; i < NTOK; i += 512) {
        int cx = min(7, max(0, (int)((sx[i] - bounds[0]) * ivx)));
        int cy = min(7, max(0, (int)((sy[i] - bounds[1]) * ivy)));
        int cz = min(7, max(0, (int)((sz[i] - bounds[2]) * ivz)));
        int m = 0;
#pragma unroll
        for (int bit = 0; bit < 3; bit++) {
            m |= ((cx >> bit) & 1) << (3 * bit + 0);
            m |= ((cy >> bit) & 1) << (3 * bit + 1);
            m |= ((cz >> bit) & 1) << (3 * bit + 2);
        }
        scell[i] = m;
        atomicAdd(&sbase[m], 1);
    }
    __syncthreads();

    if (tid == 0) {
        int run = 0;
        for (int c = 0; c < 512; c++) { int t = sbase[c]; sbase[c] = run; run += t; }
    }
    __syncthreads();

    // stable placement: one thread per cell, ascending token index
    {
        int c = tid;
        int pos = sbase[c];
        for (int i = 0; i < NTOK; i++) {
            if (scell[i] == c) {
                g_perm[b * NTOK + pos] = i;
                g_ipos[b * NTOK + i] = pos;
                float* d = g_scoords + ((size_t)b * NTOK + pos) * 3;
                d[0] = sx[i]; d[1] = sy[i]; d[2] = sz[i];
                g_skpm[b * NTOK + pos] = kpm[(size_t)b * NTOK + i];
                pos++;
            }
        }
    }
    __syncthreads();

    // per-tile bounding boxes (32 tiles of 64 sorted tokens)
    if (tid < NQT) {
        float bmn[3] = {1e30f, 1e30f, 1e30f}, bmx[3] = {-1e30f, -1e30f, -1e30f};
        for (int s = 0; s < 64; s++) {
            const float* d = g_scoords + ((size_t)b * NTOK + tid * 64 + s) * 3;
            float x = d[0], y = d[1], z = d[2];
            bmn[0] = fminf(bmn[0], x); bmx[0] = fmaxf(bmx[0], x);
            bmn[1] = fminf(bmn[1], y); bmx[1] = fmaxf(bmx[1], y);
            bmn[2] = fminf(bmn[2], z); bmx[2] = fmaxf(bmx[2], z);
        }
        float* o = g_bbox + ((size_t)b * NQT + tid) * 6;
        o[0] = bmn[0]; o[1] = bmn[1]; o[2] = bmn[2];
        o[3] = bmx[0]; o[4] = bmx[1]; o[5] = bmx[2];
    }
}

// ============================================================
// active key-tile lists: one thread per (b,h,qt)
// ============================================================
__global__ __launch_bounds__(256) void tilelist_kernel()
{
    int t = blockIdx.x * 256 + threadIdx.x;
    if (t >= B_SZ * NH * NQT) return;
    int qt = t & (NQT - 1), h = (t >> 5) & (NH - 1), b = t >> 8;
    float sp = head_spread(h);
    float cut = 9.0f * sp * sp * 1.0001f;   // tiny margin for fp safety
    const float* qb = g_bbox + ((size_t)b * NQT + qt) * 6;
    int* lst = g_tlist + (size_t)t * NQT;
    int cnt = 0;
    for (int kt = 0; kt < NQT; kt++) {
        const float* kb = g_bbox + ((size_t)b * NQT + kt) * 6;
        float gs = 0.f;
#pragma unroll
        for (int d = 0; d < 3; d++) {
            float gap = fmaxf(0.f, fmaxf(qb[d] - kb[d + 3], kb[d] - qb[d + 3]));
            gs += gap * gap;
        }
        if (gs <= cut) lst[cnt++] = kt;
    }
    g_tcnt[t] = cnt;
}

// ============================================================
// proj (R8 core): outputs scattered into SORTED order via g_ipos
// ============================================================
#define PROJ_SMEM 131072
__global__ __launch_bounds__(256) void proj_mma_kernel()
{
    extern __shared__ __align__(16) char dsm[];
    const uint32_t sb = smem_to_u32(dsm);

    const int tid = threadIdx.x;
    const int lane = tid & 31, w = tid >> 5;
    const int hp = blockIdx.x;
    const int r0 = blockIdx.y * 128;
    const int z  = blockIdx.z;

    const __nv_bfloat16* XH = g_xhi + (size_t)z * (B_SZ * NTOK * DM);
    const __nv_bfloat16* XL = g_xlo + (size_t)z * (B_SZ * NTOK * DM);
    const __nv_bfloat16* WH = g_whi + ((size_t)z * NH + hp * 2) * DK * DM;
    const __nv_bfloat16* WL = g_wlo + ((size_t)z * NH + hp * 2) * DK * DM;

    float acc[16][4];
#pragma unroll
    for (int i = 0; i < 16; i++) { acc[i][0]=0.f; acc[i][1]=0.f; acc[i][2]=0.f; acc[i][3]=0.f; }

    const uint32_t ssel = (uint32_t)(((lane >> 3) & 1) * 16);

    auto prefetch = [&](int c, int buf) {
        uint32_t base = sb + (uint32_t)buf * 65536;
#pragma unroll
        for (int t = 0; t < 4; t++) {
            int idx = tid + t * 256;
            int row = idx >> 3, cc = idx & 7;
            uint32_t off = (uint32_t)row * 128 + (((uint32_t)cc * 16) ^ ((uint32_t)(row & 7) * 16));
            size_t xoff = (size_t)(r0 + row) * DM + c * 64 + cc * 8;
            size_t woff = (size_t)row * DM + c * 64 + cc * 8;
            CP_ASYNC16(base + off,         (const char*)(XH + xoff));
            CP_ASYNC16(base + 16384 + off, (const char*)(XL + xoff));
            CP_ASYNC16(base + 32768 + off, (const char*)(WH + woff));
            CP_ASYNC16(base + 49152 + off, (const char*)(WL + woff));
        }
    };

    prefetch(0, 0); CP_COMMIT();

    const int r = w * 16 + (lane & 15);
    const uint32_t rx = (uint32_t)((r & 7) * 16);

    for (int c = 0; c < 8; c++) {
        if (c + 1 < 8) { prefetch(c + 1, (c + 1) & 1); CP_COMMIT(); CP_WAIT1(); }
        else           { CP_WAIT0(); }
        __syncthreads();

        uint32_t base = sb + (uint32_t)(c & 1) * 65536;
#pragma unroll
        for (int kb = 0; kb < 4; kb++) {
            uint32_t aoff = (uint32_t)r * 128 +
                (((uint32_t)(kb * 32 + ((lane >> 4) * 16))) ^ rx);
            uint32_t ah[4], al[4];
            LDMX4(ah, base + aoff);
            LDMX4(al, base + 16384 + aoff);
#pragma unroll
            for (int nt = 0; nt < 16; nt++) {
                int n = nt * 8 + (lane & 7);
                uint32_t boff = (uint32_t)n * 128 +
                    (((uint32_t)(kb * 32) + ssel) ^ ((uint32_t)(n & 7) * 16));
                uint32_t bh0, bh1, bl0, bl1;
                LDMX2(bh0, bh1, base + 32768 + boff);
                LDMX2(bl0, bl1, base + 49152 + boff);
                MMA16816(acc[nt], ah, bh0, bh1);
                MMA16816(acc[nt], al, bh0, bh1);
                MMA16816(acc[nt], ah, bl0, bl1);
            }
        }
        __syncthreads();
    }

    const float scale = (z == 0) ? 0.125f : 1.0f;
    __nv_bfloat16* hd = (z == 0) ? g_qhi : (z == 1) ? g_khi : g_vhi;
    __nv_bfloat16* ld = (z == 0) ? g_qlo : (z == 1) ? g_klo : g_vlo;
    const int gr0 = r0 + w * 16 + (lane >> 2);
    const int cq = 2 * (lane & 3);
#pragma unroll
    for (int rr = 0; rr < 2; rr++) {
        int gr = gr0 + rr * 8;
        int bb = gr >> 11, n = gr & (NTOK - 1);
        int spos = g_ipos[bb * NTOK + n];          // scatter to sorted order
#pragma unroll
        for (int nt = 0; nt < 16; nt++) {
            int h = hp * 2 + (nt >> 3);
            int col = (nt & 7) * 8 + cq;
            size_t base = (((size_t)bb * NH + h) * NTOK + spos) * DK + col;
            float v0 = acc[nt][2 * rr] * scale, v1 = acc[nt][2 * rr + 1] * scale;
            uint32_t l01;
            uint32_t h01 = pack_split(v0, v1, l01);
            *(uint32_t*)(hd + base) = h01;
            *(uint32_t*)(ld + base) = l01;
        }
    }
}

// ============================================================
// attention v5: sorted space + active-tile list skipping.
// q-tile 64, 128 threads, 2 CTAs/SM, triple-buffered cp.async.
// ============================================================
#define ATTN_SMEM (98304 + 3072)
__global__ __launch_bounds__(128, 2) void attn_mma_kernel()
{
    extern __shared__ __align__(16) char asm_sm[];
    char* sm = asm_sm;
    const uint32_t sb = smem_to_u32(sm);

    const int tid = threadIdx.x;
    const int lane = tid & 31;
    const int w = tid >> 5;
    const int b = blockIdx.z, h = blockIdx.y;
    const int qt = blockIdx.x;
    const int q0 = qt * 64;

    const float sp = head_spread(h);
    const float s2 = sp * sp;
    const float nine_s2 = 9.0f * s2;
    const float inv2s2 = 0.5f / s2;

    const size_t bh = ((size_t)b * NH + h) * NTOK;

    // stage Q (sorted order already)
    {
        const __nv_bfloat16* qh_g = g_qhi + (bh + q0) * DK;
        const __nv_bfloat16* ql_g = g_qlo + (bh + q0) * DK;
#pragma unroll
        for (int t = 0; t < 4; t++) {
            int idx = tid + t * 128;
            int row = idx >> 3, c = idx & 7;
            uint32_t doff = (uint32_t)row * 128 + (((uint32_t)c * 16) ^ ((uint32_t)(row & 7) * 16));
            *(uint4*)(sm + doff)        = *(const uint4*)(qh_g + (size_t)row * DK + c * 8);
            *(uint4*)(sm + 8192 + doff) = *(const uint4*)(ql_g + (size_t)row * DK + c * 8);
        }
    }
    __syncthreads();

    uint32_t aqh[4][4], aql[4][4];
    {
        int r = w * 16 + (lane & 15);
        uint32_t rx = (uint32_t)((r & 7) * 16);
#pragma unroll
        for (int ks = 0; ks < 4; ks++) {
            uint32_t cb = (uint32_t)(ks * 32 + (lane >> 4) * 16);
            uint32_t off = (uint32_t)r * 128 + (cb ^ rx);
            LDMX4(aqh[ks], sb + off);
            LDMX4(aql[ks], sb + 8192 + off);
        }
    }
    __syncthreads();

    const int g = lane >> 2;
    const int cq = 2 * (lane & 3);
    const int qr0 = q0 + w * 16 + g;
    float qx0, qy0, qz0, qx1, qy1, qz1;
    {
        const float* c0p = g_scoords + ((size_t)b * NTOK + qr0) * 3;
        const float* c1p = c0p + 24;
        qx0 = c0p[0]; qy0 = c0p[1]; qz0 = c0p[2];
        qx1 = c1p[0]; qy1 = c1p[1]; qz1 = c1p[2];
    }

    float O[8][4];
#pragma unroll
    for (int i = 0; i < 8; i++) { O[i][0]=0.f; O[i][1]=0.f; O[i][2]=0.f; O[i][3]=0.f; }
    float mr0 = -INF_F, mr1 = -INF_F, lr0 = 0.f, lr1 = 0.f;

    const __nv_bfloat16* kh_g = g_khi + bh * DK;
    const __nv_bfloat16* kl_g = g_klo + bh * DK;
    const __nv_bfloat16* vh_g = g_vhi + bh * DK;
    const __nv_bfloat16* vl_g = g_vlo + bh * DK;

    auto prefetch = [&](int mtile, int buf) {
        uint32_t base = sb + (uint32_t)buf * 32768;
        int m0 = mtile * 64;
#pragma unroll
        for (int t = 0; t < 4; t++) {
            int idx = tid + t * 128;
            int row = idx >> 3, cc = idx & 7;
            uint32_t off = (uint32_t)row * 128 + (((uint32_t)cc * 16) ^ ((uint32_t)(row & 7) * 16));
            size_t goff = (size_t)(m0 + row) * DK + cc * 8;
            CP_ASYNC16(base + off,         (const char*)(kh_g + goff));
            CP_ASYNC16(base + 8192 + off,  (const char*)(kl_g + goff));
            CP_ASYNC16(base + 16384 + off, (const char*)(vh_g + goff));
            CP_ASYNC16(base + 24576 + off, (const char*)(vl_g + goff));
        }
        uint32_t cbase = sb + 98304 + (uint32_t)buf * 1024;
        if (tid < 48)
            CP_ASYNC16(cbase + tid * 16,
                       (const char*)g_scoords + ((size_t)b * NTOK + m0) * 12 + tid * 16);
        else if (tid >= 64 && tid < 68)
            CP_ASYNC16(cbase + 768 + (tid - 64) * 16,
                       (const char*)(g_skpm + (size_t)b * NTOK + m0 + (tid - 64) * 16));
    };

    const uint32_t kxor = (uint32_t)(lane & 7) * 16;
    const uint32_t krow128 = (uint32_t)(lane & 7) * 128;
    const uint32_t ssel = (uint32_t)(((lane >> 3) & 1) * 16);
    const uint32_t vrow = (uint32_t)(lane & 15);
    const uint32_t hl = (lane >> 4) ? 8192u : 0u;

    const int tix = ((b * NH + h) * NQT + qt);
    const int nT = g_tcnt[tix];
    const int* tl = g_tlist + (size_t)tix * NQT;

    prefetch(tl[0], 0); CP_COMMIT();

    int buf = 0;
    for (int ti = 0; ti < nT; ti++) {
        if (ti + 1 < nT) {
            int nbuf = (buf == 2) ? 0 : buf + 1;
            prefetch(tl[ti + 1], nbuf); CP_COMMIT(); CP_WAIT1();
        } else {
            CP_WAIT0();
        }
        __syncthreads();

        const uint32_t base = sb + (uint32_t)buf * 32768;
        const float* mc = (const float*)(sm + 98304 + (size_t)buf * 1024);
        const unsigned char* kpms = (const unsigned char*)(sm + 98304 + (size_t)buf * 1024 + 768);

        // ---- S ----
        float S[8][4];
#pragma unroll
        for (int i = 0; i < 8; i++) { S[i][0]=0.f; S[i][1]=0.f; S[i][2]=0.f; S[i][3]=0.f; }
#pragma unroll
        for (int ks = 0; ks < 4; ks++) {
            uint32_t cb = (((uint32_t)(ks * 32)) + ssel) ^ kxor;
#pragma unroll
            for (int nt = 0; nt < 8; nt++) {
                uint32_t off = (uint32_t)nt * 1024 + krow128 + cb + hl;
                uint32_t r4[4];
                LDMX4(r4, base + off);
                MMA16816(S[nt], aqh[ks], r4[0], r4[1]);
                MMA16816(S[nt], aql[ks], r4[0], r4[1]);
                MMA16816(S[nt], aqh[ks], r4[2], r4[3]);
            }
        }

        // ---- epilogue pass A ----
        float rm0 = -INF_F, rm1 = -INF_F;
#pragma unroll
        for (int nt = 0; nt < 8; nt++) {
            int m0c = nt * 8 + cq;
            float k0x = mc[m0c*3+0], k0y = mc[m0c*3+1], k0z = mc[m0c*3+2];
            float k1x = mc[m0c*3+3], k1y = mc[m0c*3+4], k1z = mc[m0c*3+5];
            bool p0 = kpms[m0c] != 0, p1 = kpms[m0c+1] != 0;
            {
                float dx=qx0-k0x, dy=qy0-k0y, dz=qz0-k0z;
                float d2 = dx*dx+dy*dy+dz*dz;
                float s = S[nt][0];
                float v = s * __expf(copysignf(fmaxf(d2, s2)*inv2s2, -s));
                v = (d2 > nine_s2 || p0) ? -INF_F : v;
                S[nt][0]=v; rm0=fmaxf(rm0,v);
            }
            {
                float dx=qx0-k1x, dy=qy0-k1y, dz=qz0-k1z;
                float d2 = dx*dx+dy*dy+dz*dz;
                float s = S[nt][1];
                float v = s * __expf(copysignf(fmaxf(d2, s2)*inv2s2, -s));
                v = (d2 > nine_s2 || p1) ? -INF_F : v;
                S[nt][1]=v; rm0=fmaxf(rm0,v);
            }
            {
                float dx=qx1-k0x, dy=qy1-k0y, dz=qz1-k0z;
                float d2 = dx*dx+dy*dy+dz*dz;
                float s = S[nt][2];
                float v = s * __expf(copysignf(fmaxf(d2, s2)*inv2s2, -s));
                v = (d2 > nine_s2 || p0) ? -INF_F : v;
                S[nt][2]=v; rm1=fmaxf(rm1,v);
            }
            {
                float dx=qx1-k1x, dy=qy1-k1y, dz=qz1-k1z;
                float d2 = dx*dx+dy*dy+dz*dz;
                float s = S[nt][3];
                float v = s * __expf(copysignf(fmaxf(d2, s2)*inv2s2, -s));
                v = (d2 > nine_s2 || p1) ? -INF_F : v;
                S[nt][3]=v; rm1=fmaxf(rm1,v);
            }
        }
        rm0 = fmaxf(rm0, __shfl_xor_sync(0xffffffffu, rm0, 1));
        rm0 = fmaxf(rm0, __shfl_xor_sync(0xffffffffu, rm0, 2));
        rm1 = fmaxf(rm1, __shfl_xor_sync(0xffffffffu, rm1, 1));
        rm1 = fmaxf(rm1, __shfl_xor_sync(0xffffffffu, rm1, 2));

        float nm0 = fmaxf(mr0, rm0), nm1 = fmaxf(mr1, rm1);
        bool dead0 = (nm0 == -INF_F), dead1 = (nm1 == -INF_F);
        float cf0 = dead0 ? 1.f : __expf(mr0 - nm0);
        float cf1 = dead1 ? 1.f : __expf(mr1 - nm1);
#pragma unroll
        for (int nt = 0; nt < 8; nt++) {
            O[nt][0] *= cf0; O[nt][1] *= cf0;
            O[nt][2] *= cf1; O[nt][3] *= cf1;
        }
        float rs0 = 0.f, rs1 = 0.f;
#pragma unroll
        for (int nt = 0; nt < 8; nt++) {
            float p0 = dead0 ? 0.f : __expf(S[nt][0] - nm0);
            float p1 = dead0 ? 0.f : __expf(S[nt][1] - nm0);
            float p2 = dead1 ? 0.f : __expf(S[nt][2] - nm1);
            float p3 = dead1 ? 0.f : __expf(S[nt][3] - nm1);
            rs0 += p0 + p1; rs1 += p2 + p3;
            S[nt][0] = p0; S[nt][1] = p1; S[nt][2] = p2; S[nt][3] = p3;
        }
        rs0 += __shfl_xor_sync(0xffffffffu, rs0, 1);
        rs0 += __shfl_xor_sync(0xffffffffu, rs0, 2);
        rs1 += __shfl_xor_sync(0xffffffffu, rs1, 1);
        rs1 += __shfl_xor_sync(0xffffffffu, rs1, 2);
        lr0 = lr0 * cf0 + rs0; lr1 = lr1 * cf1 + rs1;
        mr0 = nm0; mr1 = nm1;

        uint32_t ph[4][4], pl[4][4];
#pragma unroll
        for (int ks = 0; ks < 4; ks++) {
            int t0 = 2 * ks, t1 = t0 + 1;
            ph[ks][0] = pack_split(S[t0][0], S[t0][1], pl[ks][0]);
            ph[ks][1] = pack_split(S[t0][2], S[t0][3], pl[ks][1]);
            ph[ks][2] = pack_split(S[t1][0], S[t1][1], pl[ks][2]);
            ph[ks][3] = pack_split(S[t1][2], S[t1][3], pl[ks][3]);
        }

        // ---- O += P V ----
#pragma unroll
        for (int ks = 0; ks < 4; ks++) {
            uint32_t roff = (uint32_t)(ks * 16 + vrow) * 128;
#pragma unroll
            for (int nt = 0; nt < 8; nt++) {
                uint32_t off = roff + (((uint32_t)nt * 16) ^ kxor) + hl;
                uint32_t r4[4];
                LDMX4T(r4, base + 16384 + off);
                MMA16816(O[nt], ph[ks], r4[0], r4[1]);
                MMA16816(O[nt], pl[ks], r4[0], r4[1]);
                MMA16816(O[nt], ph[ks], r4[2], r4[3]);
            }
        }
        buf = (buf == 2) ? 0 : buf + 1;
    }

    // scatter back to original token order
    int o0 = g_perm[b * NTOK + qr0];
    int o1 = g_perm[b * NTOK + qr0 + 8];
    float inv0 = 1.f / lr0, inv1 = 1.f / lr1;
    float* orow0 = g_o + ((size_t)b * NTOK + o0) * DM + h * DK;
    float* orow1 = g_o + ((size_t)b * NTOK + o1) * DM + h * DK;
#pragma unroll
    for (int nt = 0; nt < 8; nt++) {
        *(float2*)(orow0 + nt * 8 + cq) = make_float2(O[nt][0] * inv0, O[nt][1] * inv0);
        *(float2*)(orow1 + nt * 8 + cq) = make_float2(O[nt][2] * inv1, O[nt][3] * inv1);
    }
}

// ============================================================
// outproj (R6, proven)
// ============================================================
__global__ __launch_bounds__(256) void outproj_mma_kernel(
    const float* __restrict__ ow, const float* __restrict__ ob, float* __restrict__ out)
{
    __shared__ __align__(16) char sm[49152];
    const uint32_t sb = smem_to_u32(sm);
    char* AH = sm;          char* AL = sm + 16384;
    char* BH = sm + 32768;  char* BL = sm + 40960;

    const int tid = threadIdx.x;
    const int lane = tid & 31, w = tid >> 5;
    const int c0 = blockIdx.x * 64, r0 = blockIdx.y * 128;

    float acc[8][4];
#pragma unroll
    for (int i = 0; i < 8; i++) { acc[i][0]=0.f; acc[i][1]=0.f; acc[i][2]=0.f; acc[i][3]=0.f; }

    const uint32_t ssel = (uint32_t)(((lane >> 3) & 1) * 16);

    for (int k0 = 0; k0 < DM; k0 += 32) {
#pragma unroll
        for (int t = 0; t < 2; t++) {
            int p = tid + t * 256;
            int row = p >> 2, ch = p & 3;
            uint32_t off = (uint32_t)row * 128 + (((uint32_t)ch * 16) ^ ((uint32_t)(row & 7) * 16));
            stage8(g_o + (size_t)(r0 + row) * DM + k0 + ch * 8, AH + off, AL + off);
        }
        {
            int p = tid;
            int row = p >> 2, ch = p & 3;
            uint32_t off = (uint32_t)row * 128 + (((uint32_t)ch * 16) ^ ((uint32_t)(row & 7) * 16));
            stage8(ow + (size_t)(c0 + row) * DM + k0 + ch * 8, BH + off, BL + off);
        }
        __syncthreads();

#pragma unroll
        for (int kb = 0; kb < 2; kb++) {
            int r = w * 16 + (lane & 15);
            uint32_t aoff = (uint32_t)r * 128 +
                (((uint32_t)(kb * 32 + ((lane >> 4) * 16))) ^ ((uint32_t)(r & 7) * 16));
            uint32_t ah[4], al[4];
            LDMX4(ah, sb + (uint32_t)(AH - sm) + aoff);
            LDMX4(al, sb + (uint32_t)(AL - sm) + aoff);
#pragma unroll
            for (int nt = 0; nt < 8; nt++) {
                int n = nt * 8 + (lane & 7);
                uint32_t boff = (uint32_t)n * 128 +
                    (((uint32_t)(kb * 32) + ssel) ^ ((uint32_t)(n & 7) * 16));
                uint32_t bh0, bh1, bl0, bl1;
                LDMX2(bh0, bh1, sb + (uint32_t)(BH - sm) + boff);
                LDMX2(bl0, bl1, sb + (uint32_t)(BL - sm) + boff);
                MMA16816(acc[nt], ah, bh0, bh1);
                MMA16816(acc[nt], al, bh0, bh1);
                MMA16816(acc[nt], ah, bl0, bl1);
            }
        }
        __syncthreads();
    }

    const int gr0 = r0 + w * 16 + (lane >> 2);
    const int cq = 2 * (lane & 3);
#pragma unroll
    for (int rr = 0; rr < 2; rr++) {
        int gr = gr0 + rr * 8;
        float* orow = out + (size_t)gr * DM + c0;
#pragma unroll
        for (int nt = 0; nt < 8; nt++) {
            int col = nt * 8 + cq;
            float2 bias = *(const float2*)(ob + c0 + col);
            *(float2*)(orow + col) = make_float2(acc[nt][2 * rr] + bias.x,
                                                 acc[nt][2 * rr + 1] + bias.y);
        }
    }
}

// ---------------------------------------------------------------------------
extern "C" void kernel_launch(void* const* d_in, const int* in_sizes, int n_in,
                              void* d_out, int out_size)
{
    const float* q      = (const float*)d_in[0];
    const float* k      = (const float*)d_in[1];
    const float* v      = (const float*)d_in[2];
    const float* coords = (const float*)d_in[3];
    const unsigned char* kpm = (const unsigned char*)d_in[4];
    const float* qp     = (const float*)d_in[5];
    const float* kpj    = (const float*)d_in[6];
    const float* vp     = (const float*)d_in[7];
    const float* ow     = (const float*)d_in[8];
    const float* ob     = (const float*)d_in[9];
    float* out = (float*)d_out;

    static int attr_set = 0;
    if (!attr_set) {
        cudaFuncSetAttribute(proj_mma_kernel, cudaFuncAttributeMaxDynamicSharedMemorySize, PROJ_SMEM);
        cudaFuncSetAttribute(attn_mma_kernel, cudaFuncAttributeMaxDynamicSharedMemorySize, ATTN_SMEM);
        attr_set = 1;
    }

    sort_kernel<<<B_SZ, 512>>>(coords, kpm);
    presplit_x_kernel<<<dim3(1024, 3), 256>>>(q, k, v);
    presplit_w_kernel<<<dim3(128, 3), 256>>>(qp, kpj, vp);
    tilelist_kernel<<<2, 256>>>();
    proj_mma_kernel<<<dim3(4, 32, 3), 256, PROJ_SMEM>>>();
    attn_mma_kernel<<<dim3(NQT, NH, B_SZ), 128, ATTN_SMEM>>>();
    outproj_mma_kernel<<<dim3(8, 32), 256>>>(ow, ob, out);
}

// round 17
// speedup vs baseline: 1.3621x; 1.3621x over previous
#include <cuda_runtime.h>
#include <cuda_bf16.h>
#include <math.h>
#include <cstdint>

#define B_SZ 2
#define NTOK 2048
#define NH 8
#define DK 64
#define DM 512
#define INF_F __int_as_float(0x7f800000)

// device scratch
__device__ __align__(16) __nv_bfloat16 g_qhi[B_SZ * NH * NTOK * DK];
__device__ __align__(16) __nv_bfloat16 g_qlo[B_SZ * NH * NTOK * DK];
__device__ __align__(16) __nv_bfloat16 g_khi[B_SZ * NH * NTOK * DK];
__device__ __align__(16) __nv_bfloat16 g_klo[B_SZ * NH * NTOK * DK];
__device__ __align__(16) __nv_bfloat16 g_vhi[B_SZ * NH * NTOK * DK];
__device__ __align__(16) __nv_bfloat16 g_vlo[B_SZ * NH * NTOK * DK];
__device__ __align__(16) __nv_bfloat16 g_xhi[3 * B_SZ * NTOK * DM];
__device__ __align__(16) __nv_bfloat16 g_xlo[3 * B_SZ * NTOK * DM];
__device__ __align__(16) __nv_bfloat16 g_whi[3 * NH * DK * DM];
__device__ __align__(16) __nv_bfloat16 g_wlo[3 * NH * DK * DM];
// attention output, pre-split
__device__ __align__(16) __nv_bfloat16 g_ohi[B_SZ * NTOK * DM];
__device__ __align__(16) __nv_bfloat16 g_olo[B_SZ * NTOK * DM];
// out_w pre-split ([c][d] = [n][k] already)
__device__ __align__(16) __nv_bfloat16 g_owhi[DM * DM];
__device__ __align__(16) __nv_bfloat16 g_owlo[DM * DM];
// packed coords: x, y, z, |c|^2 + 1e30*pad
__device__ __align__(16) float4 g_cpack[B_SZ * NTOK];

// ---------------- helpers ----------------
__device__ __forceinline__ uint32_t smem_to_u32(const void* p) {
    uint32_t a;
    asm("{ .reg .u64 t; cvta.to.shared.u64 t, %1; cvt.u32.u64 %0, t; }" : "=r"(a) : "l"(p));
    return a;
}

#define LDMX2(r0, r1, addr) \
    asm volatile("ldmatrix.sync.aligned.m8n8.x2.shared.b16 {%0,%1}, [%2];" \
        : "=r"(r0), "=r"(r1) : "r"(addr))
#define LDMX4(r, addr) \
    asm volatile("ldmatrix.sync.aligned.m8n8.x4.shared.b16 {%0,%1,%2,%3}, [%4];" \
        : "=r"((r)[0]), "=r"((r)[1]), "=r"((r)[2]), "=r"((r)[3]) : "r"(addr))
#define LDMX4T(r, addr) \
    asm volatile("ldmatrix.sync.aligned.m8n8.x4.trans.shared.b16 {%0,%1,%2,%3}, [%4];" \
        : "=r"((r)[0]), "=r"((r)[1]), "=r"((r)[2]), "=r"((r)[3]) : "r"(addr))
#define MMA16816(d, a, b0, b1) \
    asm volatile("mma.sync.aligned.m16n8k16.row.col.f32.bf16.bf16.f32 " \
        "{%0,%1,%2,%3}, {%4,%5,%6,%7}, {%8,%9}, {%0,%1,%2,%3};" \
        : "+f"((d)[0]), "+f"((d)[1]), "+f"((d)[2]), "+f"((d)[3]) \
        : "r"((a)[0]), "r"((a)[1]), "r"((a)[2]), "r"((a)[3]), "r"(b0), "r"(b1))

#define CP_ASYNC16(dst, src) \
    asm volatile("cp.async.cg.shared.global [%0], [%1], 16;" :: "r"(dst), "l"(src) : "memory")
#define CP_COMMIT()  asm volatile("cp.async.commit_group;" ::: "memory")
#define CP_WAIT1()   asm volatile("cp.async.wait_group 1;" ::: "memory")
#define CP_WAIT0()   asm volatile("cp.async.wait_group 0;" ::: "memory")

__device__ __forceinline__ uint32_t pack_split(float a, float b, uint32_t& lo) {
    __nv_bfloat162 hv = __float22bfloat162_rn(make_float2(a, b));
    float ra = a - __low2float(hv);
    float rb = b - __high2float(hv);
    __nv_bfloat162 lv = __float22bfloat162_rn(make_float2(ra, rb));
    lo = *reinterpret_cast<uint32_t*>(&lv);
    return *reinterpret_cast<uint32_t*>(&hv);
}

__device__ __forceinline__ void stage8(const float* __restrict__ src,
                                       char* hi_dst, char* lo_dst)
{
    float4 a = ((const float4*)src)[0];
    float4 b = ((const float4*)src)[1];
    uint32_t l0, l1, l2, l3;
    uint32_t h0 = pack_split(a.x, a.y, l0);
    uint32_t h1 = pack_split(a.z, a.w, l1);
    uint32_t h2 = pack_split(b.x, b.y, l2);
    uint32_t h3 = pack_split(b.z, b.w, l3);
    *(uint4*)hi_dst = make_uint4(h0, h1, h2, h3);
    *(uint4*)lo_dst = make_uint4(l0, l1, l2, l3);
}

// ============================================================
// pre-pass kernels
// ============================================================
__global__ __launch_bounds__(256) void coordpack_kernel(
    const float* __restrict__ coords, const unsigned char* __restrict__ kpm)
{
    int i = blockIdx.x * 256 + threadIdx.x;
    if (i >= B_SZ * NTOK) return;
    const float* cp = coords + (size_t)i * 3;
    float x = cp[0], y = cp[1], z = cp[2];
    float kk = x * x + y * y + z * z;
    if (kpm[i]) kk += 1e30f;
    g_cpack[i] = make_float4(x, y, z, kk);
}

__global__ __launch_bounds__(256) void presplit_x_kernel(
    const float* __restrict__ q, const float* __restrict__ k, const float* __restrict__ v)
{
    const int z = blockIdx.y;
    const float* X = (z == 0) ? q : (z == 1) ? k : v;
    size_t off = ((size_t)blockIdx.x * 256 + threadIdx.x) * 8;
    size_t base = (size_t)z * (B_SZ * NTOK * DM) + off;
    stage8(X + off, (char*)(g_xhi + base), (char*)(g_xlo + base));
}

__global__ __launch_bounds__(256) void presplit_w_kernel(
    const float* __restrict__ qp, const float* __restrict__ kpj, const float* __restrict__ vp)
{
    const int z = blockIdx.y;
    const float* W = (z == 0) ? qp : (z == 1) ? kpj : vp;
    int t = blockIdx.x * 256 + threadIdx.x;
    int kc = t & 63, n = (t >> 6) & 63, h = t >> 12;
    int k0 = kc * 8;
    float f[8];
#pragma unroll
    for (int e = 0; e < 8; e++)
        f[e] = W[(size_t)h * DM * DK + (size_t)(k0 + e) * DK + n];
    uint32_t hp[4], lp[4];
#pragma unroll
    for (int e = 0; e < 4; e++)
        hp[e] = pack_split(f[2*e], f[2*e+1], lp[e]);
    size_t base = (((size_t)z * NH + h) * DK + n) * DM + k0;
    *(uint4*)(g_whi + base) = make_uint4(hp[0], hp[1], hp[2], hp[3]);
    *(uint4*)(g_wlo + base) = make_uint4(lp[0], lp[1], lp[2], lp[3]);
}

__global__ __launch_bounds__(256) void presplit_ow_kernel(const float* __restrict__ ow)
{
    size_t off = ((size_t)blockIdx.x * 256 + threadIdx.x) * 8;   // 128 blocks cover 256K elems
    stage8(ow + off, (char*)(g_owhi + off), (char*)(g_owlo + off));
}

// ============================================================
// proj (R8, proven): cp.async double-buffered
// ============================================================
#define PROJ_SMEM 131072
__global__ __launch_bounds__(256) void proj_mma_kernel()
{
    extern __shared__ __align__(16) char dsm[];
    const uint32_t sb = smem_to_u32(dsm);

    const int tid = threadIdx.x;
    const int lane = tid & 31, w = tid >> 5;
    const int hp = blockIdx.x;
    const int r0 = blockIdx.y * 128;
    const int z  = blockIdx.z;

    const __nv_bfloat16* XH = g_xhi + (size_t)z * (B_SZ * NTOK * DM);
    const __nv_bfloat16* XL = g_xlo + (size_t)z * (B_SZ * NTOK * DM);
    const __nv_bfloat16* WH = g_whi + ((size_t)z * NH + hp * 2) * DK * DM;
    const __nv_bfloat16* WL = g_wlo + ((size_t)z * NH + hp * 2) * DK * DM;

    float acc[16][4];
#pragma unroll
    for (int i = 0; i < 16; i++) { acc[i][0]=0.f; acc[i][1]=0.f; acc[i][2]=0.f; acc[i][3]=0.f; }

    const uint32_t ssel = (uint32_t)(((lane >> 3) & 1) * 16);

    auto prefetch = [&](int c, int buf) {
        uint32_t base = sb + (uint32_t)buf * 65536;
#pragma unroll
        for (int t = 0; t < 4; t++) {
            int idx = tid + t * 256;
            int row = idx >> 3, cc = idx & 7;
            uint32_t off = (uint32_t)row * 128 + (((uint32_t)cc * 16) ^ ((uint32_t)(row & 7) * 16));
            size_t xoff = (size_t)(r0 + row) * DM + c * 64 + cc * 8;
            size_t woff = (size_t)row * DM + c * 64 + cc * 8;
            CP_ASYNC16(base + off,         (const char*)(XH + xoff));
            CP_ASYNC16(base + 16384 + off, (const char*)(XL + xoff));
            CP_ASYNC16(base + 32768 + off, (const char*)(WH + woff));
            CP_ASYNC16(base + 49152 + off, (const char*)(WL + woff));
        }
    };

    prefetch(0, 0); CP_COMMIT();

    const int r = w * 16 + (lane & 15);
    const uint32_t rx = (uint32_t)((r & 7) * 16);

    for (int c = 0; c < 8; c++) {
        if (c + 1 < 8) { prefetch(c + 1, (c + 1) & 1); CP_COMMIT(); CP_WAIT1(); }
        else           { CP_WAIT0(); }
        __syncthreads();

        uint32_t base = sb + (uint32_t)(c & 1) * 65536;
#pragma unroll
        for (int kb = 0; kb < 4; kb++) {
            uint32_t aoff = (uint32_t)r * 128 +
                (((uint32_t)(kb * 32 + ((lane >> 4) * 16))) ^ rx);
            uint32_t ah[4], al[4];
            LDMX4(ah, base + aoff);
            LDMX4(al, base + 16384 + aoff);
#pragma unroll
            for (int nt = 0; nt < 16; nt++) {
                int n = nt * 8 + (lane & 7);
                uint32_t boff = (uint32_t)n * 128 +
                    (((uint32_t)(kb * 32) + ssel) ^ ((uint32_t)(n & 7) * 16));
                uint32_t bh0, bh1, bl0, bl1;
                LDMX2(bh0, bh1, base + 32768 + boff);
                LDMX2(bl0, bl1, base + 49152 + boff);
                MMA16816(acc[nt], ah, bh0, bh1);
                MMA16816(acc[nt], al, bh0, bh1);
                MMA16816(acc[nt], ah, bl0, bl1);
            }
        }
        __syncthreads();
    }

    const float scale = (z == 0) ? 0.125f : 1.0f;
    __nv_bfloat16* hd = (z == 0) ? g_qhi : (z == 1) ? g_khi : g_vhi;
    __nv_bfloat16* ld = (z == 0) ? g_qlo : (z == 1) ? g_klo : g_vlo;
    const int gr0 = r0 + w * 16 + (lane >> 2);
    const int cq = 2 * (lane & 3);
#pragma unroll
    for (int rr = 0; rr < 2; rr++) {
        int gr = gr0 + rr * 8;
        int bb = gr >> 11, n = gr & (NTOK - 1);
#pragma unroll
        for (int nt = 0; nt < 16; nt++) {
            int h = hp * 2 + (nt >> 3);
            int col = (nt & 7) * 8 + cq;
            size_t base = (((size_t)bb * NH + h) * NTOK + n) * DK + col;
            float v0 = acc[nt][2 * rr] * scale, v1 = acc[nt][2 * rr + 1] * scale;
            uint32_t l01;
            uint32_t h01 = pack_split(v0, v1, l01);
            *(uint32_t*)(hd + base) = h01;
            *(uint32_t*)(ld + base) = l01;
        }
    }
}

// ============================================================
// attention (R13 core + cpack epilogue + pre-split O output)
// q-tile 64, 128 threads, 2 CTAs/SM, triple-buffered cp.async
// ============================================================
#define ATTN_SMEM (98304 + 3072)
__global__ __launch_bounds__(128, 2) void attn_mma_kernel()
{
    extern __shared__ __align__(16) char asm_sm[];
    char* sm = asm_sm;
    const uint32_t sb = smem_to_u32(sm);

    const int tid = threadIdx.x;
    const int lane = tid & 31;
    const int w = tid >> 5;
    const int b = blockIdx.z, h = blockIdx.y;
    const int q0 = blockIdx.x * 64;

    const float tpow   = 0.98f * (float)h / 7.0f;
    const float spread = 3.7f + (powf(20.0f, tpow) - 1.0f) * (16.3f / 19.0f);
    const float s2 = spread * spread;
    const float nine_s2 = 9.0f * s2;
    const float inv2s2 = 0.5f / s2;

    const size_t bh = ((size_t)b * NH + h) * NTOK;

    // stage Q into buf0 area
    {
        const __nv_bfloat16* qh_g = g_qhi + (bh + q0) * DK;
        const __nv_bfloat16* ql_g = g_qlo + (bh + q0) * DK;
#pragma unroll
        for (int t = 0; t < 4; t++) {
            int idx = tid + t * 128;
            int row = idx >> 3, c = idx & 7;
            uint32_t doff = (uint32_t)row * 128 + (((uint32_t)c * 16) ^ ((uint32_t)(row & 7) * 16));
            *(uint4*)(sm + doff)        = *(const uint4*)(qh_g + (size_t)row * DK + c * 8);
            *(uint4*)(sm + 8192 + doff) = *(const uint4*)(ql_g + (size_t)row * DK + c * 8);
        }
    }
    __syncthreads();

    uint32_t aqh[4][4], aql[4][4];
    {
        int r = w * 16 + (lane & 15);
        uint32_t rx = (uint32_t)((r & 7) * 16);
#pragma unroll
        for (int ks = 0; ks < 4; ks++) {
            uint32_t cb = (uint32_t)(ks * 32 + (lane >> 4) * 16);
            uint32_t off = (uint32_t)r * 128 + (cb ^ rx);
            LDMX4(aqh[ks], sb + off);
            LDMX4(aql[ks], sb + 8192 + off);
        }
    }
    __syncthreads();

    const int g = lane >> 2;
    const int cq = 2 * (lane & 3);
    const int qr0 = q0 + w * 16 + g;
    float qq0, qq1, n2x0, n2y0, n2z0, n2x1, n2y1, n2z1;
    {
        float4 qc0 = g_cpack[(size_t)b * NTOK + qr0];
        float4 qc1 = g_cpack[(size_t)b * NTOK + qr0 + 8];
        qq0 = qc0.x*qc0.x + qc0.y*qc0.y + qc0.z*qc0.z;   // unpoisoned |q|^2
        qq1 = qc1.x*qc1.x + qc1.y*qc1.y + qc1.z*qc1.z;
        n2x0 = -2.f*qc0.x; n2y0 = -2.f*qc0.y; n2z0 = -2.f*qc0.z;
        n2x1 = -2.f*qc1.x; n2y1 = -2.f*qc1.y; n2z1 = -2.f*qc1.z;
    }

    float O[8][4];
#pragma unroll
    for (int i = 0; i < 8; i++) { O[i][0]=0.f; O[i][1]=0.f; O[i][2]=0.f; O[i][3]=0.f; }
    float mr0 = -INF_F, mr1 = -INF_F, lr0 = 0.f, lr1 = 0.f;

    const __nv_bfloat16* kh_g = g_khi + bh * DK;
    const __nv_bfloat16* kl_g = g_klo + bh * DK;
    const __nv_bfloat16* vh_g = g_vhi + bh * DK;
    const __nv_bfloat16* vl_g = g_vlo + bh * DK;

    auto prefetch = [&](int mtile, int buf) {
        uint32_t base = sb + (uint32_t)buf * 32768;
        int m0 = mtile * 64;
#pragma unroll
        for (int t = 0; t < 4; t++) {
            int idx = tid + t * 128;
            int row = idx >> 3, cc = idx & 7;
            uint32_t off = (uint32_t)row * 128 + (((uint32_t)cc * 16) ^ ((uint32_t)(row & 7) * 16));
            size_t goff = (size_t)(m0 + row) * DK + cc * 8;
            CP_ASYNC16(base + off,         (const char*)(kh_g + goff));
            CP_ASYNC16(base + 8192 + off,  (const char*)(kl_g + goff));
            CP_ASYNC16(base + 16384 + off, (const char*)(vh_g + goff));
            CP_ASYNC16(base + 24576 + off, (const char*)(vl_g + goff));
        }
        uint32_t cbase = sb + 98304 + (uint32_t)buf * 1024;
        if (tid < 64)
            CP_ASYNC16(cbase + tid * 16,
                       (const char*)(g_cpack + (size_t)b * NTOK + m0 + tid));
    };

    const uint32_t kxor = (uint32_t)(lane & 7) * 16;
    const uint32_t krow128 = (uint32_t)(lane & 7) * 128;
    const uint32_t ssel = (uint32_t)(((lane >> 3) & 1) * 16);
    const uint32_t vrow = (uint32_t)(lane & 15);
    const uint32_t hl = (lane >> 4) ? 8192u : 0u;

    prefetch(0, 0); CP_COMMIT();

    int buf = 0;
    for (int mt = 0; mt < NTOK / 64; mt++) {
        if (mt + 1 < NTOK / 64) {
            int nbuf = (buf == 2) ? 0 : buf + 1;
            prefetch(mt + 1, nbuf); CP_COMMIT(); CP_WAIT1();
        } else {
            CP_WAIT0();
        }
        __syncthreads();   // the ONLY barrier per tile

        const uint32_t base = sb + (uint32_t)buf * 32768;
        const float4* mc4 = (const float4*)(sm + 98304 + (size_t)buf * 1024);

        // ---- S ----
        float S[8][4];
#pragma unroll
        for (int i = 0; i < 8; i++) { S[i][0]=0.f; S[i][1]=0.f; S[i][2]=0.f; S[i][3]=0.f; }
#pragma unroll
        for (int ks = 0; ks < 4; ks++) {
            uint32_t cb = (((uint32_t)(ks * 32)) + ssel) ^ kxor;
#pragma unroll
            for (int nt = 0; nt < 8; nt++) {
                uint32_t off = (uint32_t)nt * 1024 + krow128 + cb + hl;
                uint32_t r4[4];
                LDMX4(r4, base + off);
                MMA16816(S[nt], aqh[ks], r4[0], r4[1]);
                MMA16816(S[nt], aql[ks], r4[0], r4[1]);
                MMA16816(S[nt], aqh[ks], r4[2], r4[3]);
            }
        }

        // ---- epilogue pass A: d2 = qq + kw - 2 q.k (pad folded into kw) ----
        float rm0 = -INF_F, rm1 = -INF_F;
#pragma unroll
        for (int nt = 0; nt < 8; nt++) {
            int m0c = nt * 8 + cq;
            float4 kc0 = mc4[m0c];
            float4 kc1 = mc4[m0c + 1];
            {
                float d2 = fmaf(n2x0, kc0.x, fmaf(n2y0, kc0.y, fmaf(n2z0, kc0.z, qq0 + kc0.w)));
                float s = S[nt][0];
                float v = s * __expf(copysignf(fmaxf(d2, s2) * inv2s2, -s));
                v = (d2 > nine_s2) ? -INF_F : v;
                S[nt][0] = v; rm0 = fmaxf(rm0, v);
            }
            {
                float d2 = fmaf(n2x0, kc1.x, fmaf(n2y0, kc1.y, fmaf(n2z0, kc1.z, qq0 + kc1.w)));
                float s = S[nt][1];
                float v = s * __expf(copysignf(fmaxf(d2, s2) * inv2s2, -s));
                v = (d2 > nine_s2) ? -INF_F : v;
                S[nt][1] = v; rm0 = fmaxf(rm0, v);
            }
            {
                float d2 = fmaf(n2x1, kc0.x, fmaf(n2y1, kc0.y, fmaf(n2z1, kc0.z, qq1 + kc0.w)));
                float s = S[nt][2];
                float v = s * __expf(copysignf(fmaxf(d2, s2) * inv2s2, -s));
                v = (d2 > nine_s2) ? -INF_F : v;
                S[nt][2] = v; rm1 = fmaxf(rm1, v);
            }
            {
                float d2 = fmaf(n2x1, kc1.x, fmaf(n2y1, kc1.y, fmaf(n2z1, kc1.z, qq1 + kc1.w)));
                float s = S[nt][3];
                float v = s * __expf(copysignf(fmaxf(d2, s2) * inv2s2, -s));
                v = (d2 > nine_s2) ? -INF_F : v;
                S[nt][3] = v; rm1 = fmaxf(rm1, v);
            }
        }
        rm0 = fmaxf(rm0, __shfl_xor_sync(0xffffffffu, rm0, 1));
        rm0 = fmaxf(rm0, __shfl_xor_sync(0xffffffffu, rm0, 2));
        rm1 = fmaxf(rm1, __shfl_xor_sync(0xffffffffu, rm1, 1));
        rm1 = fmaxf(rm1, __shfl_xor_sync(0xffffffffu, rm1, 2));

        float nm0 = fmaxf(mr0, rm0), nm1 = fmaxf(mr1, rm1);
        bool dead0 = (nm0 == -INF_F), dead1 = (nm1 == -INF_F);
        float cf0 = dead0 ? 1.f : __expf(mr0 - nm0);
        float cf1 = dead1 ? 1.f : __expf(mr1 - nm1);
#pragma unroll
        for (int nt = 0; nt < 8; nt++) {
            O[nt][0] *= cf0; O[nt][1] *= cf0;
            O[nt][2] *= cf1; O[nt][3] *= cf1;
        }
        float rs0 = 0.f, rs1 = 0.f;
#pragma unroll
        for (int nt = 0; nt < 8; nt++) {
            float p0 = dead0 ? 0.f : __expf(S[nt][0] - nm0);
            float p1 = dead0 ? 0.f : __expf(S[nt][1] - nm0);
            float p2 = dead1 ? 0.f : __expf(S[nt][2] - nm1);
            float p3 = dead1 ? 0.f : __expf(S[nt][3] - nm1);
            rs0 += p0 + p1; rs1 += p2 + p3;
            S[nt][0] = p0; S[nt][1] = p1; S[nt][2] = p2; S[nt][3] = p3;
        }
        rs0 += __shfl_xor_sync(0xffffffffu, rs0, 1);
        rs0 += __shfl_xor_sync(0xffffffffu, rs0, 2);
        rs1 += __shfl_xor_sync(0xffffffffu, rs1, 1);
        rs1 += __shfl_xor_sync(0xffffffffu, rs1, 2);
        lr0 = lr0 * cf0 + rs0; lr1 = lr1 * cf1 + rs1;
        mr0 = nm0; mr1 = nm1;

        uint32_t ph[4][4], pl[4][4];
#pragma unroll
        for (int ks = 0; ks < 4; ks++) {
            int t0 = 2 * ks, t1 = t0 + 1;
            ph[ks][0] = pack_split(S[t0][0], S[t0][1], pl[ks][0]);
            ph[ks][1] = pack_split(S[t0][2], S[t0][3], pl[ks][1]);
            ph[ks][2] = pack_split(S[t1][0], S[t1][1], pl[ks][2]);
            ph[ks][3] = pack_split(S[t1][2], S[t1][3], pl[ks][3]);
        }

        // ---- O += P V ----
#pragma unroll
        for (int ks = 0; ks < 4; ks++) {
            uint32_t roff = (uint32_t)(ks * 16 + vrow) * 128;
#pragma unroll
            for (int nt = 0; nt < 8; nt++) {
                uint32_t off = roff + (((uint32_t)nt * 16) ^ kxor) + hl;
                uint32_t r4[4];
                LDMX4T(r4, base + 16384 + off);
                MMA16816(O[nt], ph[ks], r4[0], r4[1]);
                MMA16816(O[nt], pl[ks], r4[0], r4[1]);
                MMA16816(O[nt], ph[ks], r4[2], r4[3]);
            }
        }
        buf = (buf == 2) ? 0 : buf + 1;
    }

    // write normalized output, PRE-SPLIT bf16 hi/lo
    float inv0 = 1.f / lr0, inv1 = 1.f / lr1;
    const size_t ob0 = ((size_t)b * NTOK + qr0) * DM + h * DK;
    const size_t ob1 = ob0 + 8 * DM;
#pragma unroll
    for (int nt = 0; nt < 8; nt++) {
        int col = nt * 8 + cq;
        uint32_t lo0, lo1;
        uint32_t hi0 = pack_split(O[nt][0] * inv0, O[nt][1] * inv0, lo0);
        uint32_t hi1 = pack_split(O[nt][2] * inv1, O[nt][3] * inv1, lo1);
        *(uint32_t*)(g_ohi + ob0 + col) = hi0;
        *(uint32_t*)(g_olo + ob0 + col) = lo0;
        *(uint32_t*)(g_ohi + ob1 + col) = hi1;
        *(uint32_t*)(g_olo + ob1 + col) = lo1;
    }
}

// ============================================================
// outproj v2: cp.async double-buffered (proj clone), 128x128 tiles
// ============================================================
__global__ __launch_bounds__(256) void outproj2_kernel(
    const float* __restrict__ ob, float* __restrict__ out)
{
    extern __shared__ __align__(16) char dsm[];
    const uint32_t sb = smem_to_u32(dsm);

    const int tid = threadIdx.x;
    const int lane = tid & 31, w = tid >> 5;
    const int c0 = blockIdx.x * 128;
    const int r0 = blockIdx.y * 128;

    float acc[16][4];
#pragma unroll
    for (int i = 0; i < 16; i++) { acc[i][0]=0.f; acc[i][1]=0.f; acc[i][2]=0.f; acc[i][3]=0.f; }

    const uint32_t ssel = (uint32_t)(((lane >> 3) & 1) * 16);

    auto prefetch = [&](int c, int buf) {
        uint32_t base = sb + (uint32_t)buf * 65536;
#pragma unroll
        for (int t = 0; t < 4; t++) {
            int idx = tid + t * 256;
            int row = idx >> 3, cc = idx & 7;
            uint32_t off = (uint32_t)row * 128 + (((uint32_t)cc * 16) ^ ((uint32_t)(row & 7) * 16));
            size_t xoff = (size_t)(r0 + row) * DM + c * 64 + cc * 8;
            size_t woff = (size_t)(c0 + row) * DM + c * 64 + cc * 8;
            CP_ASYNC16(base + off,         (const char*)(g_ohi + xoff));
            CP_ASYNC16(base + 16384 + off, (const char*)(g_olo + xoff));
            CP_ASYNC16(base + 32768 + off, (const char*)(g_owhi + woff));
            CP_ASYNC16(base + 49152 + off, (const char*)(g_owlo + woff));
        }
    };

    prefetch(0, 0); CP_COMMIT();

    const int r = w * 16 + (lane & 15);
    const uint32_t rx = (uint32_t)((r & 7) * 16);

    for (int c = 0; c < 8; c++) {
        if (c + 1 < 8) { prefetch(c + 1, (c + 1) & 1); CP_COMMIT(); CP_WAIT1(); }
        else           { CP_WAIT0(); }
        __syncthreads();

        uint32_t base = sb + (uint32_t)(c & 1) * 65536;
#pragma unroll
        for (int kb = 0; kb < 4; kb++) {
            uint32_t aoff = (uint32_t)r * 128 +
                (((uint32_t)(kb * 32 + ((lane >> 4) * 16))) ^ rx);
            uint32_t ah[4], al[4];
            LDMX4(ah, base + aoff);
            LDMX4(al, base + 16384 + aoff);
#pragma unroll
            for (int nt = 0; nt < 16; nt++) {
                int n = nt * 8 + (lane & 7);
                uint32_t boff = (uint32_t)n * 128 +
                    (((uint32_t)(kb * 32) + ssel) ^ ((uint32_t)(n & 7) * 16));
                uint32_t bh0, bh1, bl0, bl1;
                LDMX2(bh0, bh1, base + 32768 + boff);
                LDMX2(bl0, bl1, base + 49152 + boff);
                MMA16816(acc[nt], ah, bh0, bh1);
                MMA16816(acc[nt], al, bh0, bh1);
                MMA16816(acc[nt], ah, bl0, bl1);
            }
        }
        __syncthreads();
    }

    const int gr0 = r0 + w * 16 + (lane >> 2);
    const int cq = 2 * (lane & 3);
#pragma unroll
    for (int rr = 0; rr < 2; rr++) {
        int gr = gr0 + rr * 8;
        float* orow = out + (size_t)gr * DM + c0;
#pragma unroll
        for (int nt = 0; nt < 16; nt++) {
            int col = nt * 8 + cq;
            float2 bias = *(const float2*)(ob + c0 + col);
            *(float2*)(orow + col) = make_float2(acc[nt][2 * rr] + bias.x,
                                                 acc[nt][2 * rr + 1] + bias.y);
        }
    }
}

// ---------------------------------------------------------------------------
extern "C" void kernel_launch(void* const* d_in, const int* in_sizes, int n_in,
                              void* d_out, int out_size)
{
    const float* q      = (const float*)d_in[0];
    const float* k      = (const float*)d_in[1];
    const float* v      = (const float*)d_in[2];
    const float* coords = (const float*)d_in[3];
    const unsigned char* kpm = (const unsigned char*)d_in[4];
    const float* qp     = (const float*)d_in[5];
    const float* kpj    = (const float*)d_in[6];
    const float* vp     = (const float*)d_in[7];
    const float* ow     = (const float*)d_in[8];
    const float* ob     = (const float*)d_in[9];
    float* out = (float*)d_out;

    static int attr_set = 0;
    if (!attr_set) {
        cudaFuncSetAttribute(proj_mma_kernel, cudaFuncAttributeMaxDynamicSharedMemorySize, PROJ_SMEM);
        cudaFuncSetAttribute(attn_mma_kernel, cudaFuncAttributeMaxDynamicSharedMemorySize, ATTN_SMEM);
        cudaFuncSetAttribute(outproj2_kernel, cudaFuncAttributeMaxDynamicSharedMemorySize, PROJ_SMEM);
        attr_set = 1;
    }

    coordpack_kernel<<<16, 256>>>(coords, kpm);
    presplit_x_kernel<<<dim3(1024, 3), 256>>>(q, k, v);
    presplit_w_kernel<<<dim3(128, 3), 256>>>(qp, kpj, vp);
    presplit_ow_kernel<<<128, 256>>>(ow);
    proj_mma_kernel<<<dim3(4, 32, 3), 256, PROJ_SMEM>>>();
    attn_mma_kernel<<<dim3(NTOK / 64, NH, B_SZ), 128, ATTN_SMEM>>>();
    outproj2_kernel<<<dim3(4, 32), 256, PROJ_SMEM>>>(ob, out);
}